// round 7
// baseline (speedup 1.0000x reference)
#include <cuda_runtime.h>
#include <math_constants.h>

#define NN 50000
#define EE 800000
#define DD 128
#define ET (EE + NN)
#define NB ((NN + 255) / 256)        // 196 scan blocks
#define BN_EPS 1e-12f
#define SLOPE 0.2f
#define KT 16
#define SKEW(c) ((c) + 4 * ((c) >> 5))

// ---------------- scratch ----------------
__device__ __align__(16) float g_h [NN * DD];
__device__ __align__(16) float g_x1[NN * DD];
__device__ float g_hs[NN];
__device__ float g_hd[NN];
__device__ int   g_cnt[NN];
__device__ int   g_rowoff[NN + 1];
__device__ int   g_fill[NN];
__device__ unsigned long long g_scanstate[NB];   // [63:32]=status(1=agg,2=incl), [31:0]=value
__device__ int   g_csr[ET];

// ============ GEMM (128x128 tile, 8x8/thread, FFMA2) + fused attention dots ============
__global__ __launch_bounds__(256) void gemm_dots_kernel(
    const float* __restrict__ X, const float* __restrict__ W,
    float* __restrict__ H,
    const float* __restrict__ asrc, const float* __restrict__ adst)
{
    __shared__ float sXT[KT][132];
    __shared__ float sW [KT][140];

    const int tid  = threadIdx.x;
    const int row0 = blockIdx.x * 128;
    const int ty   = tid >> 4;
    const int tx   = tid & 15;
    const int r0   = ty * 8;
    const int c0   = tx * 8;
    const int p0   = SKEW(c0);

    unsigned long long accp[8][4];
#pragma unroll
    for (int i = 0; i < 8; i++)
#pragma unroll
        for (int j = 0; j < 4; j++) accp[i][j] = 0ull;

    for (int k0 = 0; k0 < 128; k0 += KT) {
#pragma unroll
        for (int it = 0; it < 2; it++) {
            int e  = it * 1024 + tid * 4;
            int r  = e >> 4;
            int kk = e & 15;
            int gr = row0 + r;
            float4 v = make_float4(0.f, 0.f, 0.f, 0.f);
            if (gr < NN) v = *(const float4*)&X[(size_t)gr * 128 + k0 + kk];
            sXT[kk + 0][r] = v.x; sXT[kk + 1][r] = v.y;
            sXT[kk + 2][r] = v.z; sXT[kk + 3][r] = v.w;
        }
#pragma unroll
        for (int it = 0; it < 2; it++) {
            int e = it * 1024 + tid * 4;
            int k = e >> 7;
            int c = e & 127;
            float4 v = *(const float4*)&W[(size_t)(k0 + k) * 128 + c];
            *(float4*)&sW[k][SKEW(c)] = v;
        }
        __syncthreads();

#pragma unroll
        for (int k = 0; k < KT; k++) {
            float xv[8];
            *(float4*)&xv[0] = *(const float4*)&sXT[k][r0];
            *(float4*)&xv[4] = *(const float4*)&sXT[k][r0 + 4];
            ulonglong2 wA = *(const ulonglong2*)&sW[k][p0];
            ulonglong2 wB = *(const ulonglong2*)&sW[k][p0 + 4];
#pragma unroll
            for (int i = 0; i < 8; i++) {
                unsigned long long xx;
                asm("mov.b64 %0, {%1, %1};" : "=l"(xx) : "f"(xv[i]));
                asm("fma.rn.f32x2 %0, %1, %2, %0;" : "+l"(accp[i][0]) : "l"(xx), "l"(wA.x));
                asm("fma.rn.f32x2 %0, %1, %2, %0;" : "+l"(accp[i][1]) : "l"(xx), "l"(wA.y));
                asm("fma.rn.f32x2 %0, %1, %2, %0;" : "+l"(accp[i][2]) : "l"(xx), "l"(wB.x));
                asm("fma.rn.f32x2 %0, %1, %2, %0;" : "+l"(accp[i][3]) : "l"(xx), "l"(wB.y));
            }
        }
        __syncthreads();
    }

    float h[8][8];
#pragma unroll
    for (int i = 0; i < 8; i++)
#pragma unroll
        for (int j = 0; j < 4; j++)
            asm("mov.b64 {%0, %1}, %2;" : "=f"(h[i][2 * j]), "=f"(h[i][2 * j + 1]) : "l"(accp[i][j]));

    float av[8], bv[8];
    *(float4*)&av[0] = *(const float4*)&asrc[c0];
    *(float4*)&av[4] = *(const float4*)&asrc[c0 + 4];
    *(float4*)&bv[0] = *(const float4*)&adst[c0];
    *(float4*)&bv[4] = *(const float4*)&adst[c0 + 4];

#pragma unroll
    for (int i = 0; i < 8; i++) {
        int gr = row0 + r0 + i;
        if (gr < NN) {
            *(float4*)&H[(size_t)gr * 128 + c0]     = make_float4(h[i][0], h[i][1], h[i][2], h[i][3]);
            *(float4*)&H[(size_t)gr * 128 + c0 + 4] = make_float4(h[i][4], h[i][5], h[i][6], h[i][7]);
        }
        float ps = 0.f, pd = 0.f;
#pragma unroll
        for (int j = 0; j < 8; j++) { ps += h[i][j] * av[j]; pd += h[i][j] * bv[j]; }
#pragma unroll
        for (int o = 1; o < 16; o <<= 1) {
            ps += __shfl_xor_sync(0xffffffffu, ps, o);
            pd += __shfl_xor_sync(0xffffffffu, pd, o);
        }
        if (tx == 0 && gr < NN) { g_hs[gr] = ps; g_hd[gr] = pd; }
    }
}

// ================= CSR build =================
__global__ __launch_bounds__(256) void csr_init_kernel()
{
    int i = blockIdx.x * blockDim.x + threadIdx.x;
    if (i < NN) { g_cnt[i] = 1; g_fill[i] = 0; }   // self loop counted
    if (i < NB) g_scanstate[i] = 0ull;
    if (i == 0) g_rowoff[0] = 0;
}

__global__ __launch_bounds__(256) void csr_hist_kernel(const int* __restrict__ edst)
{
    int t = blockIdx.x * blockDim.x + threadIdx.x;
    if (t < EE) atomicAdd(&g_cnt[edst[t]], 1);
}

__device__ __forceinline__ int block_incl_scan_256(int v, int tid)
{
    int lane = tid & 31, w = tid >> 5;
#pragma unroll
    for (int o = 1; o < 32; o <<= 1) {
        int n = __shfl_up_sync(0xffffffffu, v, o);
        if (lane >= o) v += n;
    }
    __shared__ int wsum[8];
    if (lane == 31) wsum[w] = v;
    __syncthreads();
    if (tid < 8) {
        int x = wsum[tid];
#pragma unroll
        for (int o = 1; o < 8; o <<= 1) {
            int n = __shfl_up_sync(0xffu, x, o);
            if (tid >= o) x += n;
        }
        wsum[tid] = x;
    }
    __syncthreads();
    if (w > 0) v += wsum[w - 1];
    return v;
}

// single-pass exclusive-prefix via decoupled lookback (196 blocks, all resident)
__global__ __launch_bounds__(256) void scan_kernel()
{
    const int t = threadIdx.x, b = blockIdx.x;
    const int i = b * 256 + t;
    int v = (i < NN) ? g_cnt[i] : 0;
    int incl = block_incl_scan_256(v, t);

    __shared__ int s_agg;
    __shared__ int s_prefix;
    if (t == 255) s_agg = incl;
    __syncthreads();

    if (t == 0) {
        int agg = s_agg;
        if (b == 0) {
            *(volatile unsigned long long*)&g_scanstate[0] =
                (2ull << 32) | (unsigned int)agg;
            s_prefix = 0;
        } else {
            // publish aggregate
            *(volatile unsigned long long*)&g_scanstate[b] =
                (1ull << 32) | (unsigned int)agg;
            // lookback
            int sum = 0;
            for (int p = b - 1; p >= 0; p--) {
                unsigned long long st;
                do { st = *(volatile unsigned long long*)&g_scanstate[p]; }
                while ((st >> 32) == 0ull);
                sum += (int)(st & 0xffffffffull);
                if ((st >> 32) == 2ull) break;
            }
            s_prefix = sum;
            *(volatile unsigned long long*)&g_scanstate[b] =
                (2ull << 32) | (unsigned int)(sum + agg);
        }
    }
    __syncthreads();
    if (i < NN) g_rowoff[i + 1] = incl + s_prefix;
}

__global__ __launch_bounds__(256) void csr_scatter_kernel(
    const int* __restrict__ esrc, const int* __restrict__ edst)
{
    int t = blockIdx.x * blockDim.x + threadIdx.x;
    if (t >= ET) return;
    int s, d;
    if (t < EE) { s = esrc[t]; d = edst[t]; }
    else        { s = t - EE; d = s; }
    int pos = g_rowoff[d] + atomicAdd(&g_fill[d], 1);
    g_csr[pos] = s;
}

// ========== fused: online-softmax aggregate + bias + BN + ReLU (1 pass) ==========
__global__ __launch_bounds__(256) void agg_kernel(
    float* __restrict__ outbuf,
    const float* __restrict__ bias,  const float* __restrict__ gamma,
    const float* __restrict__ beta,  const float* __restrict__ mean,
    const float* __restrict__ var)
{
    int node = (int)(((size_t)blockIdx.x * blockDim.x + threadIdx.x) >> 5);
    int lane = threadIdx.x & 31;
    if (node >= NN) return;

    const int off = g_rowoff[node];
    const int end = g_rowoff[node + 1];
    const float hd_d = g_hd[node];

    float m    = -CUDART_INF_F;   // running max (warp-uniform)
    float ssum = 0.f;             // per-lane partial sum of exp
    float4 acc = make_float4(0.f, 0.f, 0.f, 0.f);

    for (int base = off; base < end; base += 32) {
        int rem = end - base; if (rem > 32) rem = 32;
        int s = 0;
        float e = -CUDART_INF_F;
        if (lane < rem) {
            s = g_csr[base + lane];
            e = g_hs[s] + hd_d;
            e = e > 0.f ? e : SLOPE * e;
        }
        // chunk max
        float cm = e;
#pragma unroll
        for (int o = 16; o; o >>= 1) cm = fmaxf(cm, __shfl_xor_sync(0xffffffffu, cm, o));
        float newm = fmaxf(m, cm);
        float scale = __expf(m - newm);       // m=-inf on first chunk -> 0
        ssum *= scale;
        acc.x *= scale; acc.y *= scale; acc.z *= scale; acc.w *= scale;
        m = newm;

        float ee = (lane < rem) ? __expf(e - m) : 0.f;
        ssum += ee;

        if (rem == 32) {
#pragma unroll 8
            for (int j = 0; j < 32; j++) {
                int   sj  = __shfl_sync(0xffffffffu, s,  j);
                float eej = __shfl_sync(0xffffffffu, ee, j);
                float4 h4 = ((const float4*)g_h)[(size_t)sj * 32 + lane];
                acc.x += eej * h4.x; acc.y += eej * h4.y;
                acc.z += eej * h4.z; acc.w += eej * h4.w;
            }
        } else {
            for (int j = 0; j < rem; j++) {
                int   sj  = __shfl_sync(0xffffffffu, s,  j);
                float eej = __shfl_sync(0xffffffffu, ee, j);
                float4 h4 = ((const float4*)g_h)[(size_t)sj * 32 + lane];
                acc.x += eej * h4.x; acc.y += eej * h4.y;
                acc.z += eej * h4.z; acc.w += eej * h4.w;
            }
        }
    }
#pragma unroll
    for (int o = 16; o; o >>= 1) ssum += __shfl_xor_sync(0xffffffffu, ssum, o);
    float inv = 1.f / ssum;

    float4 ga = ((const float4*)gamma)[lane];
    float4 va = ((const float4*)var)[lane];
    float4 bi = ((const float4*)bias)[lane];
    float4 mu = ((const float4*)mean)[lane];
    float4 be = ((const float4*)beta)[lane];
    float4 sc, sh, o4;
    sc.x = ga.x * rsqrtf(va.x + BN_EPS); sh.x = (bi.x - mu.x) * sc.x + be.x;
    sc.y = ga.y * rsqrtf(va.y + BN_EPS); sh.y = (bi.y - mu.y) * sc.y + be.y;
    sc.z = ga.z * rsqrtf(va.z + BN_EPS); sh.z = (bi.z - mu.z) * sc.z + be.z;
    sc.w = ga.w * rsqrtf(va.w + BN_EPS); sh.w = (bi.w - mu.w) * sc.w + be.w;
    o4.x = fmaxf(fmaf(acc.x * inv, sc.x, sh.x), 0.f);
    o4.y = fmaxf(fmaf(acc.y * inv, sc.y, sh.y), 0.f);
    o4.z = fmaxf(fmaf(acc.z * inv, sc.z, sh.z), 0.f);
    o4.w = fmaxf(fmaf(acc.w * inv, sc.w, sh.w), 0.f);
    ((float4*)outbuf)[(size_t)node * 32 + lane] = o4;
}

// ---------------- host orchestration ----------------
static void run_layer(const float* x_in, float* agg_out, float* p_h,
                      const float* W, const float* asrc, const float* adst,
                      const float* bias, const float* gamma, const float* beta,
                      const float* mean, const float* var)
{
    gemm_dots_kernel<<<(NN + 127) / 128, 256>>>(x_in, W, p_h, asrc, adst);
    agg_kernel<<<(NN * 32 + 255) / 256, 256>>>(agg_out, bias, gamma, beta, mean, var);
}

extern "C" void kernel_launch(void* const* d_in, const int* in_sizes, int n_in,
                              void* d_out, int out_size)
{
    const float* x     = (const float*)d_in[0];
    const int*   eidx  = (const int*)d_in[1];
    const float* Ws    = (const float*)d_in[2];
    const float* a_src = (const float*)d_in[3];
    const float* a_dst = (const float*)d_in[4];
    const float* bias  = (const float*)d_in[5];
    const float* gamma = (const float*)d_in[6];
    const float* beta  = (const float*)d_in[7];
    const float* mean  = (const float*)d_in[8];
    const float* var   = (const float*)d_in[9];
    float*       out   = (float*)d_out;

    const int* esrc = eidx;
    const int* edst = eidx + EE;

    float* p_h;  cudaGetSymbolAddress((void**)&p_h, g_h);
    float* p_x1; cudaGetSymbolAddress((void**)&p_x1, g_x1);

    csr_init_kernel<<<(NN + 255) / 256, 256>>>();
    csr_hist_kernel<<<(EE + 255) / 256, 256>>>(edst);
    scan_kernel<<<NB, 256>>>();
    csr_scatter_kernel<<<(ET + 255) / 256, 256>>>(esrc, edst);

    run_layer(x, p_x1, p_h, Ws, a_src, a_dst, bias, gamma, beta, mean, var);
    run_layer(p_x1, out, p_h,
              Ws + DD * DD, a_src + DD, a_dst + DD, bias + DD,
              gamma + DD, beta + DD, mean + DD, var + DD);
}

// round 8
// speedup vs baseline: 1.1212x; 1.1212x over previous
#include <cuda_runtime.h>
#include <cuda_fp16.h>
#include <math_constants.h>

#define NN 50000
#define EE 800000
#define DD 128
#define ET (EE + NN)
#define NB ((NN + 255) / 256)
#define BN_EPS 1e-12f
#define SLOPE 0.2f
#define KT 16
#define SKEW(c) ((c) + 4 * ((c) >> 5))

// ---------------- scratch ----------------
__device__ __align__(16) __half g_h [NN * DD];   // h = x@W, fp16 (gather path only)
__device__ __align__(16) float  g_x1[NN * DD];   // layer-1 output (fp32)
__device__ float g_hs[NN];
__device__ float g_hd[NN];
__device__ int   g_cnt[NN];
__device__ int   g_rowoff[NN + 1];
__device__ int   g_fill[NN];
__device__ unsigned long long g_scanstate[NB];
__device__ int   g_csr[ET];

// ============ GEMM (128x128 tile, 8x8/thread, FFMA2) + fused dots; fp16 h out ============
__global__ __launch_bounds__(256) void gemm_dots_kernel(
    const float* __restrict__ X, const float* __restrict__ W,
    __half* __restrict__ H,
    const float* __restrict__ asrc, const float* __restrict__ adst)
{
    __shared__ float sXT[KT][132];
    __shared__ float sW [KT][140];

    const int tid  = threadIdx.x;
    const int row0 = blockIdx.x * 128;
    const int ty   = tid >> 4;
    const int tx   = tid & 15;
    const int r0   = ty * 8;
    const int c0   = tx * 8;
    const int p0   = SKEW(c0);

    unsigned long long accp[8][4];
#pragma unroll
    for (int i = 0; i < 8; i++)
#pragma unroll
        for (int j = 0; j < 4; j++) accp[i][j] = 0ull;

    for (int k0 = 0; k0 < 128; k0 += KT) {
#pragma unroll
        for (int it = 0; it < 2; it++) {
            int e  = it * 1024 + tid * 4;
            int r  = e >> 4;
            int kk = e & 15;
            int gr = row0 + r;
            float4 v = make_float4(0.f, 0.f, 0.f, 0.f);
            if (gr < NN) v = *(const float4*)&X[(size_t)gr * 128 + k0 + kk];
            sXT[kk + 0][r] = v.x; sXT[kk + 1][r] = v.y;
            sXT[kk + 2][r] = v.z; sXT[kk + 3][r] = v.w;
        }
#pragma unroll
        for (int it = 0; it < 2; it++) {
            int e = it * 1024 + tid * 4;
            int k = e >> 7;
            int c = e & 127;
            float4 v = *(const float4*)&W[(size_t)(k0 + k) * 128 + c];
            *(float4*)&sW[k][SKEW(c)] = v;
        }
        __syncthreads();

#pragma unroll
        for (int k = 0; k < KT; k++) {
            float xv[8];
            *(float4*)&xv[0] = *(const float4*)&sXT[k][r0];
            *(float4*)&xv[4] = *(const float4*)&sXT[k][r0 + 4];
            ulonglong2 wA = *(const ulonglong2*)&sW[k][p0];
            ulonglong2 wB = *(const ulonglong2*)&sW[k][p0 + 4];
#pragma unroll
            for (int i = 0; i < 8; i++) {
                unsigned long long xx;
                asm("mov.b64 %0, {%1, %1};" : "=l"(xx) : "f"(xv[i]));
                asm("fma.rn.f32x2 %0, %1, %2, %0;" : "+l"(accp[i][0]) : "l"(xx), "l"(wA.x));
                asm("fma.rn.f32x2 %0, %1, %2, %0;" : "+l"(accp[i][1]) : "l"(xx), "l"(wA.y));
                asm("fma.rn.f32x2 %0, %1, %2, %0;" : "+l"(accp[i][2]) : "l"(xx), "l"(wB.x));
                asm("fma.rn.f32x2 %0, %1, %2, %0;" : "+l"(accp[i][3]) : "l"(xx), "l"(wB.y));
            }
        }
        __syncthreads();
    }

    float h[8][8];
#pragma unroll
    for (int i = 0; i < 8; i++)
#pragma unroll
        for (int j = 0; j < 4; j++)
            asm("mov.b64 {%0, %1}, %2;" : "=f"(h[i][2 * j]), "=f"(h[i][2 * j + 1]) : "l"(accp[i][j]));

    float av[8], bv[8];
    *(float4*)&av[0] = *(const float4*)&asrc[c0];
    *(float4*)&av[4] = *(const float4*)&asrc[c0 + 4];
    *(float4*)&bv[0] = *(const float4*)&adst[c0];
    *(float4*)&bv[4] = *(const float4*)&adst[c0 + 4];

#pragma unroll
    for (int i = 0; i < 8; i++) {
        int gr = row0 + r0 + i;
        if (gr < NN) {
            // fp16 store: 8 cols = 16B
            __half2 q0 = __floats2half2_rn(h[i][0], h[i][1]);
            __half2 q1 = __floats2half2_rn(h[i][2], h[i][3]);
            __half2 q2 = __floats2half2_rn(h[i][4], h[i][5]);
            __half2 q3 = __floats2half2_rn(h[i][6], h[i][7]);
            uint4 u;
            u.x = *(unsigned*)&q0; u.y = *(unsigned*)&q1;
            u.z = *(unsigned*)&q2; u.w = *(unsigned*)&q3;
            *(uint4*)&H[(size_t)gr * 128 + c0] = u;
        }
        // dots from full-precision registers
        float ps = 0.f, pd = 0.f;
#pragma unroll
        for (int j = 0; j < 8; j++) { ps += h[i][j] * av[j]; pd += h[i][j] * bv[j]; }
#pragma unroll
        for (int o = 1; o < 16; o <<= 1) {
            ps += __shfl_xor_sync(0xffffffffu, ps, o);
            pd += __shfl_xor_sync(0xffffffffu, pd, o);
        }
        if (tx == 0 && gr < NN) { g_hs[gr] = ps; g_hd[gr] = pd; }
    }
}

// ================= CSR build =================
__global__ __launch_bounds__(256) void csr_init_kernel()
{
    int i = blockIdx.x * blockDim.x + threadIdx.x;
    if (i < NN) { g_cnt[i] = 1; g_fill[i] = 0; }
    if (i < NB) g_scanstate[i] = 0ull;
    if (i == 0) g_rowoff[0] = 0;
}

__global__ __launch_bounds__(256) void csr_hist_kernel(const int* __restrict__ edst)
{
    int t = blockIdx.x * blockDim.x + threadIdx.x;
    if (t < EE) atomicAdd(&g_cnt[edst[t]], 1);
}

__device__ __forceinline__ int block_incl_scan_256(int v, int tid)
{
    int lane = tid & 31, w = tid >> 5;
#pragma unroll
    for (int o = 1; o < 32; o <<= 1) {
        int n = __shfl_up_sync(0xffffffffu, v, o);
        if (lane >= o) v += n;
    }
    __shared__ int wsum[8];
    if (lane == 31) wsum[w] = v;
    __syncthreads();
    if (tid < 8) {
        int x = wsum[tid];
#pragma unroll
        for (int o = 1; o < 8; o <<= 1) {
            int n = __shfl_up_sync(0xffu, x, o);
            if (tid >= o) x += n;
        }
        wsum[tid] = x;
    }
    __syncthreads();
    if (w > 0) v += wsum[w - 1];
    return v;
}

__global__ __launch_bounds__(256) void scan_kernel()
{
    const int t = threadIdx.x, b = blockIdx.x;
    const int i = b * 256 + t;
    int v = (i < NN) ? g_cnt[i] : 0;
    int incl = block_incl_scan_256(v, t);

    __shared__ int s_agg;
    __shared__ int s_prefix;
    if (t == 255) s_agg = incl;
    __syncthreads();

    if (t == 0) {
        int agg = s_agg;
        if (b == 0) {
            *(volatile unsigned long long*)&g_scanstate[0] = (2ull << 32) | (unsigned)agg;
            s_prefix = 0;
        } else {
            *(volatile unsigned long long*)&g_scanstate[b] = (1ull << 32) | (unsigned)agg;
            int sum = 0;
            for (int p = b - 1; p >= 0; p--) {
                unsigned long long st;
                do { st = *(volatile unsigned long long*)&g_scanstate[p]; }
                while ((st >> 32) == 0ull);
                sum += (int)(st & 0xffffffffull);
                if ((st >> 32) == 2ull) break;
            }
            s_prefix = sum;
            *(volatile unsigned long long*)&g_scanstate[b] = (2ull << 32) | (unsigned)(sum + agg);
        }
    }
    __syncthreads();
    if (i < NN) g_rowoff[i + 1] = incl + s_prefix;
}

__global__ __launch_bounds__(256) void csr_scatter_kernel(
    const int* __restrict__ esrc, const int* __restrict__ edst)
{
    int t = blockIdx.x * blockDim.x + threadIdx.x;
    if (t >= ET) return;
    int s, d;
    if (t < EE) { s = esrc[t]; d = edst[t]; }
    else        { s = t - EE; d = s; }
    int pos = g_rowoff[d] + atomicAdd(&g_fill[d], 1);
    g_csr[pos] = s;
}

// ========== fused: online-softmax aggregate (fp16 gather) + bias + BN + ReLU ==========
__global__ __launch_bounds__(256) void agg_kernel(
    float* __restrict__ outbuf,
    const float* __restrict__ bias,  const float* __restrict__ gamma,
    const float* __restrict__ beta,  const float* __restrict__ mean,
    const float* __restrict__ var)
{
    int node = (int)(((size_t)blockIdx.x * blockDim.x + threadIdx.x) >> 5);
    int lane = threadIdx.x & 31;
    if (node >= NN) return;

    const int off = g_rowoff[node];
    const int end = g_rowoff[node + 1];
    const float hd_d = g_hd[node];

    float m    = -CUDART_INF_F;
    float ssum = 0.f;
    float4 acc = make_float4(0.f, 0.f, 0.f, 0.f);

    for (int base = off; base < end; base += 32) {
        int rem = end - base; if (rem > 32) rem = 32;
        int s = 0;
        float e = -CUDART_INF_F;
        if (lane < rem) {
            s = g_csr[base + lane];
            e = g_hs[s] + hd_d;
            e = e > 0.f ? e : SLOPE * e;
        }
        float cm = e;
#pragma unroll
        for (int o = 16; o; o >>= 1) cm = fmaxf(cm, __shfl_xor_sync(0xffffffffu, cm, o));
        float newm = fmaxf(m, cm);
        float scale = __expf(m - newm);
        ssum *= scale;
        acc.x *= scale; acc.y *= scale; acc.z *= scale; acc.w *= scale;
        m = newm;

        float ee = (lane < rem) ? __expf(e - m) : 0.f;
        ssum += ee;

        if (rem == 32) {
#pragma unroll 8
            for (int j = 0; j < 32; j++) {
                int   sj  = __shfl_sync(0xffffffffu, s,  j);
                float eej = __shfl_sync(0xffffffffu, ee, j);
                uint2 pk = *(const uint2*)&g_h[(size_t)sj * 128 + lane * 4];
                float2 f0 = __half22float2(*(__half2*)&pk.x);
                float2 f1 = __half22float2(*(__half2*)&pk.y);
                acc.x += eej * f0.x; acc.y += eej * f0.y;
                acc.z += eej * f1.x; acc.w += eej * f1.y;
            }
        } else {
            for (int j = 0; j < rem; j++) {
                int   sj  = __shfl_sync(0xffffffffu, s,  j);
                float eej = __shfl_sync(0xffffffffu, ee, j);
                uint2 pk = *(const uint2*)&g_h[(size_t)sj * 128 + lane * 4];
                float2 f0 = __half22float2(*(__half2*)&pk.x);
                float2 f1 = __half22float2(*(__half2*)&pk.y);
                acc.x += eej * f0.x; acc.y += eej * f0.y;
                acc.z += eej * f1.x; acc.w += eej * f1.y;
            }
        }
    }
#pragma unroll
    for (int o = 16; o; o >>= 1) ssum += __shfl_xor_sync(0xffffffffu, ssum, o);
    float inv = 1.f / ssum;

    float4 ga = ((const float4*)gamma)[lane];
    float4 va = ((const float4*)var)[lane];
    float4 bi = ((const float4*)bias)[lane];
    float4 mu = ((const float4*)mean)[lane];
    float4 be = ((const float4*)beta)[lane];
    float4 sc, sh, o4;
    sc.x = ga.x * rsqrtf(va.x + BN_EPS); sh.x = (bi.x - mu.x) * sc.x + be.x;
    sc.y = ga.y * rsqrtf(va.y + BN_EPS); sh.y = (bi.y - mu.y) * sc.y + be.y;
    sc.z = ga.z * rsqrtf(va.z + BN_EPS); sh.z = (bi.z - mu.z) * sc.z + be.z;
    sc.w = ga.w * rsqrtf(va.w + BN_EPS); sh.w = (bi.w - mu.w) * sc.w + be.w;
    o4.x = fmaxf(fmaf(acc.x * inv, sc.x, sh.x), 0.f);
    o4.y = fmaxf(fmaf(acc.y * inv, sc.y, sh.y), 0.f);
    o4.z = fmaxf(fmaf(acc.z * inv, sc.z, sh.z), 0.f);
    o4.w = fmaxf(fmaf(acc.w * inv, sc.w, sh.w), 0.f);
    ((float4*)outbuf)[(size_t)node * 32 + lane] = o4;
}

// ---------------- host orchestration ----------------
static void run_layer(const float* x_in, float* agg_out, __half* p_h,
                      const float* W, const float* asrc, const float* adst,
                      const float* bias, const float* gamma, const float* beta,
                      const float* mean, const float* var)
{
    gemm_dots_kernel<<<(NN + 127) / 128, 256>>>(x_in, W, p_h, asrc, adst);
    agg_kernel<<<(NN * 32 + 255) / 256, 256>>>(agg_out, bias, gamma, beta, mean, var);
}

extern "C" void kernel_launch(void* const* d_in, const int* in_sizes, int n_in,
                              void* d_out, int out_size)
{
    const float* x     = (const float*)d_in[0];
    const int*   eidx  = (const int*)d_in[1];
    const float* Ws    = (const float*)d_in[2];
    const float* a_src = (const float*)d_in[3];
    const float* a_dst = (const float*)d_in[4];
    const float* bias  = (const float*)d_in[5];
    const float* gamma = (const float*)d_in[6];
    const float* beta  = (const float*)d_in[7];
    const float* mean  = (const float*)d_in[8];
    const float* var   = (const float*)d_in[9];
    float*       out   = (float*)d_out;

    const int* esrc = eidx;
    const int* edst = eidx + EE;

    __half* p_h; cudaGetSymbolAddress((void**)&p_h, g_h);
    float* p_x1; cudaGetSymbolAddress((void**)&p_x1, g_x1);

    csr_init_kernel<<<(NN + 255) / 256, 256>>>();
    csr_hist_kernel<<<(EE + 255) / 256, 256>>>(edst);
    scan_kernel<<<NB, 256>>>();
    csr_scatter_kernel<<<(ET + 255) / 256, 256>>>(esrc, edst);

    run_layer(x, p_x1, p_h, Ws, a_src, a_dst, bias, gamma, beta, mean, var);
    run_layer(p_x1, out, p_h,
              Ws + DD * DD, a_src + DD, a_dst + DD, bias + DD,
              gamma + DD, beta + DD, mean + DD, var + DD);
}

// round 9
// speedup vs baseline: 1.4951x; 1.3336x over previous
#include <cuda_runtime.h>
#include <cuda_fp16.h>
#include <math_constants.h>

#define NN 50000
#define EE 800000
#define DD 128
#define ET (EE + NN)
#define NB ((NN + 255) / 256)
#define BN_EPS 1e-12f
#define SLOPE 0.2f

// smem layout for gemm: sX[128][136] half | sW[128][136] half | sA[256] float
#define LDH 136
#define SMEM_X_BYTES (128 * LDH * 2)
#define SMEM_GEMM_BYTES (2 * SMEM_X_BYTES + 256 * 4)

// ---------------- scratch ----------------
__device__ __align__(16) __half g_h [NN * DD];   // h = x@W, fp16 (gather path)
__device__ __align__(16) float  g_x1[NN * DD];   // layer-1 output (fp32)
__device__ float g_hs[NN];
__device__ float g_hd[NN];
__device__ int   g_cnt[NN];
__device__ int   g_rowoff[NN + 1];
__device__ int   g_fill[NN];
__device__ unsigned long long g_scanstate[NB];
__device__ int   g_csr[ET];

// ---------------- mma helpers ----------------
__device__ __forceinline__ unsigned smem_u32(const void* p) {
    return (unsigned)__cvta_generic_to_shared(p);
}
__device__ __forceinline__ void ldmA(unsigned addr, unsigned& a0, unsigned& a1,
                                     unsigned& a2, unsigned& a3) {
    asm volatile("ldmatrix.sync.aligned.m8n8.x4.shared.b16 {%0,%1,%2,%3}, [%4];"
                 : "=r"(a0), "=r"(a1), "=r"(a2), "=r"(a3) : "r"(addr));
}
__device__ __forceinline__ void ldmBT(unsigned addr, unsigned& b0, unsigned& b1) {
    asm volatile("ldmatrix.sync.aligned.m8n8.x2.trans.shared.b16 {%0,%1}, [%2];"
                 : "=r"(b0), "=r"(b1) : "r"(addr));
}
__device__ __forceinline__ void mma16816(float& d0, float& d1, float& d2, float& d3,
                                         unsigned a0, unsigned a1, unsigned a2, unsigned a3,
                                         unsigned b0, unsigned b1) {
    asm volatile("mma.sync.aligned.m16n8k16.row.col.f32.f16.f16.f32 "
                 "{%0,%1,%2,%3}, {%4,%5,%6,%7}, {%8,%9}, {%0,%1,%2,%3};"
                 : "+f"(d0), "+f"(d1), "+f"(d2), "+f"(d3)
                 : "r"(a0), "r"(a1), "r"(a2), "r"(a3), "r"(b0), "r"(b1));
}

// ============ GEMM via HMMA (fp16 in, f32 acc) + fused attention dots ============
__global__ __launch_bounds__(256) void gemm_dots_kernel(
    const float* __restrict__ X, const float* __restrict__ W,
    __half* __restrict__ H,
    const float* __restrict__ asrc, const float* __restrict__ adst)
{
    extern __shared__ char smem[];
    __half* sX = (__half*)smem;                        // [128][LDH]
    __half* sW = (__half*)(smem + SMEM_X_BYTES);       // [128][LDH]
    float*  sA = (float*) (smem + 2 * SMEM_X_BYTES);   // asrc[128] | adst[128]

    const int tid  = threadIdx.x;
    const int wid  = tid >> 5;
    const int lane = tid & 31;
    const int row0 = blockIdx.x * 128;

    // stage X (fp32 -> fp16)
#pragma unroll
    for (int it = 0; it < 16; it++) {
        int e  = it * 256 + tid;
        int r  = e >> 5, c4 = e & 31;
        int gr = row0 + r;
        float4 v = (gr < NN) ? *(const float4*)&X[(size_t)gr * 128 + c4 * 4]
                             : make_float4(0.f, 0.f, 0.f, 0.f);
        __half2 h0 = __floats2half2_rn(v.x, v.y);
        __half2 h1 = __floats2half2_rn(v.z, v.w);
        *(uint2*)&sX[r * LDH + c4 * 4] = make_uint2(*(unsigned*)&h0, *(unsigned*)&h1);
    }
    // stage W (fp32 -> fp16)
#pragma unroll
    for (int it = 0; it < 16; it++) {
        int e = it * 256 + tid;
        int k = e >> 5, c4 = e & 31;
        float4 v = *(const float4*)&W[(size_t)k * 128 + c4 * 4];
        __half2 h0 = __floats2half2_rn(v.x, v.y);
        __half2 h1 = __floats2half2_rn(v.z, v.w);
        *(uint2*)&sW[k * LDH + c4 * 4] = make_uint2(*(unsigned*)&h0, *(unsigned*)&h1);
    }
    sA[tid] = (tid < 128) ? asrc[tid] : adst[tid - 128];
    __syncthreads();

    const int r0 = wid * 16;
    float d[16][4];
#pragma unroll
    for (int nt = 0; nt < 16; nt++)
#pragma unroll
        for (int j = 0; j < 4; j++) d[nt][j] = 0.f;

    // A address: row = r0 + (lane&15), col = kk + 8*(lane>>4)
    unsigned aBase = smem_u32(&sX[(r0 + (lane & 15)) * LDH + 8 * (lane >> 4)]);
    unsigned wBase = smem_u32(sW);

#pragma unroll
    for (int k = 0; k < 8; k++) {
        unsigned a0, a1, a2, a3;
        ldmA(aBase + (16 * k) * 2, a0, a1, a2, a3);
        unsigned bRow = wBase + ((16 * k + (lane & 15)) * LDH) * 2;
#pragma unroll
        for (int nt = 0; nt < 16; nt++) {
            unsigned b0, b1;
            ldmBT(bRow + nt * 8 * 2, b0, b1);
            mma16816(d[nt][0], d[nt][1], d[nt][2], d[nt][3], a0, a1, a2, a3, b0, b1);
        }
    }

    // epilogue: fp16 h store + attention dots (f32)
    const int qr   = lane >> 2;
    const int qc   = (lane & 3) * 2;
    const int rowA = row0 + r0 + qr;
    const int rowB = rowA + 8;
    float psA = 0.f, pdA = 0.f, psB = 0.f, pdB = 0.f;

#pragma unroll
    for (int nt = 0; nt < 16; nt++) {
        int c = nt * 8 + qc;
        float2 av = *(float2*)&sA[c];
        float2 bv = *(float2*)&sA[128 + c];
        psA += d[nt][0] * av.x + d[nt][1] * av.y;
        pdA += d[nt][0] * bv.x + d[nt][1] * bv.y;
        psB += d[nt][2] * av.x + d[nt][3] * av.y;
        pdB += d[nt][2] * bv.x + d[nt][3] * bv.y;
        if (rowA < NN) {
            __half2 hh = __floats2half2_rn(d[nt][0], d[nt][1]);
            *(__half2*)&H[(size_t)rowA * 128 + c] = hh;
        }
        if (rowB < NN) {
            __half2 hh = __floats2half2_rn(d[nt][2], d[nt][3]);
            *(__half2*)&H[(size_t)rowB * 128 + c] = hh;
        }
    }
#pragma unroll
    for (int o = 1; o <= 2; o <<= 1) {
        psA += __shfl_xor_sync(0xffffffffu, psA, o);
        pdA += __shfl_xor_sync(0xffffffffu, pdA, o);
        psB += __shfl_xor_sync(0xffffffffu, psB, o);
        pdB += __shfl_xor_sync(0xffffffffu, pdB, o);
    }
    if ((lane & 3) == 0) {
        if (rowA < NN) { g_hs[rowA] = psA; g_hd[rowA] = pdA; }
        if (rowB < NN) { g_hs[rowB] = psB; g_hd[rowB] = pdB; }
    }
}

// ================= CSR build =================
__global__ __launch_bounds__(256) void csr_init_kernel()
{
    int i = blockIdx.x * blockDim.x + threadIdx.x;
    if (i < NN) { g_cnt[i] = 1; g_fill[i] = 0; }
    if (i < NB) g_scanstate[i] = 0ull;
    if (i == 0) g_rowoff[0] = 0;
}

__global__ __launch_bounds__(256) void csr_hist_kernel(const int* __restrict__ edst)
{
    int t = blockIdx.x * blockDim.x + threadIdx.x;
    if (t < EE) atomicAdd(&g_cnt[edst[t]], 1);
}

__device__ __forceinline__ int block_incl_scan_256(int v, int tid)
{
    int lane = tid & 31, w = tid >> 5;
#pragma unroll
    for (int o = 1; o < 32; o <<= 1) {
        int n = __shfl_up_sync(0xffffffffu, v, o);
        if (lane >= o) v += n;
    }
    __shared__ int wsum[8];
    if (lane == 31) wsum[w] = v;
    __syncthreads();
    if (tid < 8) {
        int x = wsum[tid];
#pragma unroll
        for (int o = 1; o < 8; o <<= 1) {
            int n = __shfl_up_sync(0xffu, x, o);
            if (tid >= o) x += n;
        }
        wsum[tid] = x;
    }
    __syncthreads();
    if (w > 0) v += wsum[w - 1];
    return v;
}

__global__ __launch_bounds__(256) void scan_kernel()
{
    const int t = threadIdx.x, b = blockIdx.x;
    const int i = b * 256 + t;
    int v = (i < NN) ? g_cnt[i] : 0;
    int incl = block_incl_scan_256(v, t);

    __shared__ int s_agg;
    __shared__ int s_prefix;
    if (t == 255) s_agg = incl;
    __syncthreads();

    if (t == 0) {
        int agg = s_agg;
        if (b == 0) {
            *(volatile unsigned long long*)&g_scanstate[0] = (2ull << 32) | (unsigned)agg;
            s_prefix = 0;
        } else {
            *(volatile unsigned long long*)&g_scanstate[b] = (1ull << 32) | (unsigned)agg;
            int sum = 0;
            for (int p = b - 1; p >= 0; p--) {
                unsigned long long st;
                do { st = *(volatile unsigned long long*)&g_scanstate[p]; }
                while ((st >> 32) == 0ull);
                sum += (int)(st & 0xffffffffull);
                if ((st >> 32) == 2ull) break;
            }
            s_prefix = sum;
            *(volatile unsigned long long*)&g_scanstate[b] = (2ull << 32) | (unsigned)(sum + agg);
        }
    }
    __syncthreads();
    if (i < NN) g_rowoff[i + 1] = incl + s_prefix;
}

__global__ __launch_bounds__(256) void csr_scatter_kernel(
    const int* __restrict__ esrc, const int* __restrict__ edst)
{
    int t = blockIdx.x * blockDim.x + threadIdx.x;
    if (t >= ET) return;
    int s, d;
    if (t < EE) { s = esrc[t]; d = edst[t]; }
    else        { s = t - EE; d = s; }
    int pos = g_rowoff[d] + atomicAdd(&g_fill[d], 1);
    g_csr[pos] = s;
}

// ========== fused: online-softmax aggregate (fp16 gather) + bias + BN + ReLU ==========
__global__ __launch_bounds__(256) void agg_kernel(
    float* __restrict__ outbuf,
    const float* __restrict__ bias,  const float* __restrict__ gamma,
    const float* __restrict__ beta,  const float* __restrict__ mean,
    const float* __restrict__ var)
{
    int node = (int)(((size_t)blockIdx.x * blockDim.x + threadIdx.x) >> 5);
    int lane = threadIdx.x & 31;
    if (node >= NN) return;

    const int off = g_rowoff[node];
    const int end = g_rowoff[node + 1];
    const float hd_d = g_hd[node];

    float m    = -CUDART_INF_F;
    float ssum = 0.f;
    float4 acc = make_float4(0.f, 0.f, 0.f, 0.f);

    for (int base = off; base < end; base += 32) {
        int rem = end - base; if (rem > 32) rem = 32;
        int s = 0;
        float e = -CUDART_INF_F;
        if (lane < rem) {
            s = g_csr[base + lane];
            e = g_hs[s] + hd_d;
            e = e > 0.f ? e : SLOPE * e;
        }
        float cm = e;
#pragma unroll
        for (int o = 16; o; o >>= 1) cm = fmaxf(cm, __shfl_xor_sync(0xffffffffu, cm, o));
        float newm = fmaxf(m, cm);
        float scale = __expf(m - newm);
        ssum *= scale;
        acc.x *= scale; acc.y *= scale; acc.z *= scale; acc.w *= scale;
        m = newm;

        float ee = (lane < rem) ? __expf(e - m) : 0.f;
        ssum += ee;

        if (rem == 32) {
#pragma unroll 8
            for (int j = 0; j < 32; j++) {
                int   sj  = __shfl_sync(0xffffffffu, s,  j);
                float eej = __shfl_sync(0xffffffffu, ee, j);
                uint2 pk = *(const uint2*)&g_h[(size_t)sj * 128 + lane * 4];
                float2 f0 = __half22float2(*(__half2*)&pk.x);
                float2 f1 = __half22float2(*(__half2*)&pk.y);
                acc.x += eej * f0.x; acc.y += eej * f0.y;
                acc.z += eej * f1.x; acc.w += eej * f1.y;
            }
        } else {
            for (int j = 0; j < rem; j++) {
                int   sj  = __shfl_sync(0xffffffffu, s,  j);
                float eej = __shfl_sync(0xffffffffu, ee, j);
                uint2 pk = *(const uint2*)&g_h[(size_t)sj * 128 + lane * 4];
                float2 f0 = __half22float2(*(__half2*)&pk.x);
                float2 f1 = __half22float2(*(__half2*)&pk.y);
                acc.x += eej * f0.x; acc.y += eej * f0.y;
                acc.z += eej * f1.x; acc.w += eej * f1.y;
            }
        }
    }
#pragma unroll
    for (int o = 16; o; o >>= 1) ssum += __shfl_xor_sync(0xffffffffu, ssum, o);
    float inv = 1.f / ssum;

    float4 ga = ((const float4*)gamma)[lane];
    float4 va = ((const float4*)var)[lane];
    float4 bi = ((const float4*)bias)[lane];
    float4 mu = ((const float4*)mean)[lane];
    float4 be = ((const float4*)beta)[lane];
    float4 sc, sh, o4;
    sc.x = ga.x * rsqrtf(va.x + BN_EPS); sh.x = (bi.x - mu.x) * sc.x + be.x;
    sc.y = ga.y * rsqrtf(va.y + BN_EPS); sh.y = (bi.y - mu.y) * sc.y + be.y;
    sc.z = ga.z * rsqrtf(va.z + BN_EPS); sh.z = (bi.z - mu.z) * sc.z + be.z;
    sc.w = ga.w * rsqrtf(va.w + BN_EPS); sh.w = (bi.w - mu.w) * sc.w + be.w;
    o4.x = fmaxf(fmaf(acc.x * inv, sc.x, sh.x), 0.f);
    o4.y = fmaxf(fmaf(acc.y * inv, sc.y, sh.y), 0.f);
    o4.z = fmaxf(fmaf(acc.z * inv, sc.z, sh.z), 0.f);
    o4.w = fmaxf(fmaf(acc.w * inv, sc.w, sh.w), 0.f);
    ((float4*)outbuf)[(size_t)node * 32 + lane] = o4;
}

// ---------------- host orchestration ----------------
static void run_layer(const float* x_in, float* agg_out, __half* p_h,
                      const float* W, const float* asrc, const float* adst,
                      const float* bias, const float* gamma, const float* beta,
                      const float* mean, const float* var)
{
    gemm_dots_kernel<<<(NN + 127) / 128, 256, SMEM_GEMM_BYTES>>>(x_in, W, p_h, asrc, adst);
    agg_kernel<<<(NN * 32 + 255) / 256, 256>>>(agg_out, bias, gamma, beta, mean, var);
}

extern "C" void kernel_launch(void* const* d_in, const int* in_sizes, int n_in,
                              void* d_out, int out_size)
{
    const float* x     = (const float*)d_in[0];
    const int*   eidx  = (const int*)d_in[1];
    const float* Ws    = (const float*)d_in[2];
    const float* a_src = (const float*)d_in[3];
    const float* a_dst = (const float*)d_in[4];
    const float* bias  = (const float*)d_in[5];
    const float* gamma = (const float*)d_in[6];
    const float* beta  = (const float*)d_in[7];
    const float* mean  = (const float*)d_in[8];
    const float* var   = (const float*)d_in[9];
    float*       out   = (float*)d_out;

    const int* esrc = eidx;
    const int* edst = eidx + EE;

    __half* p_h; cudaGetSymbolAddress((void**)&p_h, g_h);
    float* p_x1; cudaGetSymbolAddress((void**)&p_x1, g_x1);

    cudaFuncSetAttribute(gemm_dots_kernel,
                         cudaFuncAttributeMaxDynamicSharedMemorySize, SMEM_GEMM_BYTES);

    csr_init_kernel<<<(NN + 255) / 256, 256>>>();
    csr_hist_kernel<<<(EE + 255) / 256, 256>>>(edst);
    scan_kernel<<<NB, 256>>>();
    csr_scatter_kernel<<<(ET + 255) / 256, 256>>>(esrc, edst);

    run_layer(x, p_x1, p_h, Ws, a_src, a_dst, bias, gamma, beta, mean, var);
    run_layer(p_x1, out, p_h,
              Ws + DD * DD, a_src + DD, a_dst + DD, bias + DD,
              gamma + DD, beta + DD, mean + DD, var + DD);
}

// round 10
// speedup vs baseline: 1.5405x; 1.0303x over previous
#include <cuda_runtime.h>
#include <cuda_fp16.h>
#include <math_constants.h>

#define NN 50000
#define EE 800000
#define DD 128
#define ET (EE + NN)
#define NB ((NN + 255) / 256)
#define BN_EPS 1e-12f
#define SLOPE 0.2f

#define LDH 136
#define SMEM_X_BYTES (128 * LDH * 2)
#define SMEM_GEMM_BYTES (2 * SMEM_X_BYTES + 256 * 4)

// ---------------- scratch ----------------
__device__ __align__(16) __half g_h [NN * DD];
__device__ __align__(16) float  g_x1[NN * DD];
__device__ float g_hs[NN];
__device__ float g_hd[NN];
__device__ int   g_cnt[NN];
__device__ int   g_rowoff[NN + 1];
__device__ int   g_eoff[EE];                 // per-edge slot within its dst row
__device__ unsigned long long g_scanstate[NB];
__device__ int   g_csr[ET];

// ---------------- mma helpers ----------------
__device__ __forceinline__ unsigned smem_u32(const void* p) {
    return (unsigned)__cvta_generic_to_shared(p);
}
__device__ __forceinline__ void ldmA(unsigned addr, unsigned& a0, unsigned& a1,
                                     unsigned& a2, unsigned& a3) {
    asm volatile("ldmatrix.sync.aligned.m8n8.x4.shared.b16 {%0,%1,%2,%3}, [%4];"
                 : "=r"(a0), "=r"(a1), "=r"(a2), "=r"(a3) : "r"(addr));
}
__device__ __forceinline__ void ldmBT(unsigned addr, unsigned& b0, unsigned& b1) {
    asm volatile("ldmatrix.sync.aligned.m8n8.x2.trans.shared.b16 {%0,%1}, [%2];"
                 : "=r"(b0), "=r"(b1) : "r"(addr));
}
__device__ __forceinline__ void mma16816(float& d0, float& d1, float& d2, float& d3,
                                         unsigned a0, unsigned a1, unsigned a2, unsigned a3,
                                         unsigned b0, unsigned b1) {
    asm volatile("mma.sync.aligned.m16n8k16.row.col.f32.f16.f16.f32 "
                 "{%0,%1,%2,%3}, {%4,%5,%6,%7}, {%8,%9}, {%0,%1,%2,%3};"
                 : "+f"(d0), "+f"(d1), "+f"(d2), "+f"(d3)
                 : "r"(a0), "r"(a1), "r"(a2), "r"(a3), "r"(b0), "r"(b1));
}

// ============ GEMM via HMMA (fp16 in, f32 acc) + fused attention dots ============
__global__ __launch_bounds__(256) void gemm_dots_kernel(
    const float* __restrict__ X, const float* __restrict__ W,
    __half* __restrict__ H,
    const float* __restrict__ asrc, const float* __restrict__ adst)
{
    extern __shared__ char smem[];
    __half* sX = (__half*)smem;
    __half* sW = (__half*)(smem + SMEM_X_BYTES);
    float*  sA = (float*) (smem + 2 * SMEM_X_BYTES);

    const int tid  = threadIdx.x;
    const int wid  = tid >> 5;
    const int lane = tid & 31;
    const int row0 = blockIdx.x * 128;

#pragma unroll
    for (int it = 0; it < 16; it++) {
        int e  = it * 256 + tid;
        int r  = e >> 5, c4 = e & 31;
        int gr = row0 + r;
        float4 v = (gr < NN) ? *(const float4*)&X[(size_t)gr * 128 + c4 * 4]
                             : make_float4(0.f, 0.f, 0.f, 0.f);
        __half2 h0 = __floats2half2_rn(v.x, v.y);
        __half2 h1 = __floats2half2_rn(v.z, v.w);
        *(uint2*)&sX[r * LDH + c4 * 4] = make_uint2(*(unsigned*)&h0, *(unsigned*)&h1);
    }
#pragma unroll
    for (int it = 0; it < 16; it++) {
        int e = it * 256 + tid;
        int k = e >> 5, c4 = e & 31;
        float4 v = *(const float4*)&W[(size_t)k * 128 + c4 * 4];
        __half2 h0 = __floats2half2_rn(v.x, v.y);
        __half2 h1 = __floats2half2_rn(v.z, v.w);
        *(uint2*)&sW[k * LDH + c4 * 4] = make_uint2(*(unsigned*)&h0, *(unsigned*)&h1);
    }
    sA[tid] = (tid < 128) ? asrc[tid] : adst[tid - 128];
    __syncthreads();

    const int r0 = wid * 16;
    float d[16][4];
#pragma unroll
    for (int nt = 0; nt < 16; nt++)
#pragma unroll
        for (int j = 0; j < 4; j++) d[nt][j] = 0.f;

    unsigned aBase = smem_u32(&sX[(r0 + (lane & 15)) * LDH + 8 * (lane >> 4)]);
    unsigned wBase = smem_u32(sW);

#pragma unroll
    for (int k = 0; k < 8; k++) {
        unsigned a0, a1, a2, a3;
        ldmA(aBase + (16 * k) * 2, a0, a1, a2, a3);
        unsigned bRow = wBase + ((16 * k + (lane & 15)) * LDH) * 2;
#pragma unroll
        for (int nt = 0; nt < 16; nt++) {
            unsigned b0, b1;
            ldmBT(bRow + nt * 8 * 2, b0, b1);
            mma16816(d[nt][0], d[nt][1], d[nt][2], d[nt][3], a0, a1, a2, a3, b0, b1);
        }
    }

    const int qr   = lane >> 2;
    const int qc   = (lane & 3) * 2;
    const int rowA = row0 + r0 + qr;
    const int rowB = rowA + 8;
    float psA = 0.f, pdA = 0.f, psB = 0.f, pdB = 0.f;

#pragma unroll
    for (int nt = 0; nt < 16; nt++) {
        int c = nt * 8 + qc;
        float2 av = *(float2*)&sA[c];
        float2 bv = *(float2*)&sA[128 + c];
        psA += d[nt][0] * av.x + d[nt][1] * av.y;
        pdA += d[nt][0] * bv.x + d[nt][1] * bv.y;
        psB += d[nt][2] * av.x + d[nt][3] * av.y;
        pdB += d[nt][2] * bv.x + d[nt][3] * bv.y;
        if (rowA < NN) {
            __half2 hh = __floats2half2_rn(d[nt][0], d[nt][1]);
            *(__half2*)&H[(size_t)rowA * 128 + c] = hh;
        }
        if (rowB < NN) {
            __half2 hh = __floats2half2_rn(d[nt][2], d[nt][3]);
            *(__half2*)&H[(size_t)rowB * 128 + c] = hh;
        }
    }
#pragma unroll
    for (int o = 1; o <= 2; o <<= 1) {
        psA += __shfl_xor_sync(0xffffffffu, psA, o);
        pdA += __shfl_xor_sync(0xffffffffu, pdA, o);
        psB += __shfl_xor_sync(0xffffffffu, psB, o);
        pdB += __shfl_xor_sync(0xffffffffu, pdB, o);
    }
    if ((lane & 3) == 0) {
        if (rowA < NN) { g_hs[rowA] = psA; g_hd[rowA] = pdA; }
        if (rowB < NN) { g_hs[rowB] = psB; g_hd[rowB] = pdB; }
    }
}

// ================= CSR build =================
__global__ __launch_bounds__(256) void csr_init_kernel()
{
    int i = blockIdx.x * blockDim.x + threadIdx.x;
    if (i < NN) g_cnt[i] = 1;           // slot 0 reserved for the self loop
    if (i < NB) g_scanstate[i] = 0ull;
    if (i == 0) g_rowoff[0] = 0;
}

// hist also records each edge's slot within its destination row
__global__ __launch_bounds__(256) void csr_hist_kernel(const int* __restrict__ edst)
{
    int t = blockIdx.x * blockDim.x + threadIdx.x;
    if (t < EE) g_eoff[t] = atomicAdd(&g_cnt[edst[t]], 1);
}

__device__ __forceinline__ int block_incl_scan_256(int v, int tid)
{
    int lane = tid & 31, w = tid >> 5;
#pragma unroll
    for (int o = 1; o < 32; o <<= 1) {
        int n = __shfl_up_sync(0xffffffffu, v, o);
        if (lane >= o) v += n;
    }
    __shared__ int wsum[8];
    if (lane == 31) wsum[w] = v;
    __syncthreads();
    if (tid < 8) {
        int x = wsum[tid];
#pragma unroll
        for (int o = 1; o < 8; o <<= 1) {
            int n = __shfl_up_sync(0xffu, x, o);
            if (tid >= o) x += n;
        }
        wsum[tid] = x;
    }
    __syncthreads();
    if (w > 0) v += wsum[w - 1];
    return v;
}

__global__ __launch_bounds__(256) void scan_kernel()
{
    const int t = threadIdx.x, b = blockIdx.x;
    const int i = b * 256 + t;
    int v = (i < NN) ? g_cnt[i] : 0;
    int incl = block_incl_scan_256(v, t);

    __shared__ int s_agg;
    __shared__ int s_prefix;
    if (t == 255) s_agg = incl;
    __syncthreads();

    if (t == 0) {
        int agg = s_agg;
        if (b == 0) {
            *(volatile unsigned long long*)&g_scanstate[0] = (2ull << 32) | (unsigned)agg;
            s_prefix = 0;
        } else {
            *(volatile unsigned long long*)&g_scanstate[b] = (1ull << 32) | (unsigned)agg;
            int sum = 0;
            for (int p = b - 1; p >= 0; p--) {
                unsigned long long st;
                do { st = *(volatile unsigned long long*)&g_scanstate[p]; }
                while ((st >> 32) == 0ull);
                sum += (int)(st & 0xffffffffull);
                if ((st >> 32) == 2ull) break;
            }
            s_prefix = sum;
            *(volatile unsigned long long*)&g_scanstate[b] = (2ull << 32) | (unsigned)(sum + agg);
        }
    }
    __syncthreads();
    if (i < NN) g_rowoff[i + 1] = incl + s_prefix;
}

// scatter: atomic-free (slot precomputed in hist)
__global__ __launch_bounds__(256) void csr_scatter_kernel(
    const int* __restrict__ esrc, const int* __restrict__ edst)
{
    int t = blockIdx.x * blockDim.x + threadIdx.x;
    if (t >= ET) return;
    if (t < EE) {
        int d = edst[t];
        g_csr[g_rowoff[d] + g_eoff[t]] = esrc[t];
    } else {
        int i = t - EE;
        g_csr[g_rowoff[i]] = i;      // self loop in slot 0
    }
}

// ========== fused: online-softmax aggregate (fp16 gather) + bias + BN + ReLU ==========
__global__ __launch_bounds__(256) void agg_kernel(
    float* __restrict__ outbuf,
    const float* __restrict__ bias,  const float* __restrict__ gamma,
    const float* __restrict__ beta,  const float* __restrict__ mean,
    const float* __restrict__ var)
{
    int node = (int)(((size_t)blockIdx.x * blockDim.x + threadIdx.x) >> 5);
    int lane = threadIdx.x & 31;
    if (node >= NN) return;

    const int off = g_rowoff[node];
    const int end = g_rowoff[node + 1];
    const float hd_d = g_hd[node];

    float m    = -CUDART_INF_F;
    float ssum = 0.f;
    float4 acc = make_float4(0.f, 0.f, 0.f, 0.f);

    for (int base = off; base < end; base += 32) {
        int rem = end - base; if (rem > 32) rem = 32;
        int s = 0;
        float e = -CUDART_INF_F;
        if (lane < rem) {
            s = g_csr[base + lane];
            e = g_hs[s] + hd_d;
            e = e > 0.f ? e : SLOPE * e;
        }
        float cm = e;
#pragma unroll
        for (int o = 16; o; o >>= 1) cm = fmaxf(cm, __shfl_xor_sync(0xffffffffu, cm, o));
        float newm = fmaxf(m, cm);
        float scale = __expf(m - newm);
        ssum *= scale;
        acc.x *= scale; acc.y *= scale; acc.z *= scale; acc.w *= scale;
        m = newm;

        float ee = (lane < rem) ? __expf(e - m) : 0.f;
        ssum += ee;

        if (rem == 32) {
#pragma unroll 16
            for (int j = 0; j < 32; j++) {
                int   sj  = __shfl_sync(0xffffffffu, s,  j);
                float eej = __shfl_sync(0xffffffffu, ee, j);
                uint2 pk = *(const uint2*)&g_h[(size_t)sj * 128 + lane * 4];
                float2 f0 = __half22float2(*(__half2*)&pk.x);
                float2 f1 = __half22float2(*(__half2*)&pk.y);
                acc.x += eej * f0.x; acc.y += eej * f0.y;
                acc.z += eej * f1.x; acc.w += eej * f1.y;
            }
        } else {
            for (int j = 0; j < rem; j++) {
                int   sj  = __shfl_sync(0xffffffffu, s,  j);
                float eej = __shfl_sync(0xffffffffu, ee, j);
                uint2 pk = *(const uint2*)&g_h[(size_t)sj * 128 + lane * 4];
                float2 f0 = __half22float2(*(__half2*)&pk.x);
                float2 f1 = __half22float2(*(__half2*)&pk.y);
                acc.x += eej * f0.x; acc.y += eej * f0.y;
                acc.z += eej * f1.x; acc.w += eej * f1.y;
            }
        }
    }
#pragma unroll
    for (int o = 16; o; o >>= 1) ssum += __shfl_xor_sync(0xffffffffu, ssum, o);
    float inv = 1.f / ssum;

    float4 ga = ((const float4*)gamma)[lane];
    float4 va = ((const float4*)var)[lane];
    float4 bi = ((const float4*)bias)[lane];
    float4 mu = ((const float4*)mean)[lane];
    float4 be = ((const float4*)beta)[lane];
    float4 sc, sh, o4;
    sc.x = ga.x * rsqrtf(va.x + BN_EPS); sh.x = (bi.x - mu.x) * sc.x + be.x;
    sc.y = ga.y * rsqrtf(va.y + BN_EPS); sh.y = (bi.y - mu.y) * sc.y + be.y;
    sc.z = ga.z * rsqrtf(va.z + BN_EPS); sh.z = (bi.z - mu.z) * sc.z + be.z;
    sc.w = ga.w * rsqrtf(va.w + BN_EPS); sh.w = (bi.w - mu.w) * sc.w + be.w;
    o4.x = fmaxf(fmaf(acc.x * inv, sc.x, sh.x), 0.f);
    o4.y = fmaxf(fmaf(acc.y * inv, sc.y, sh.y), 0.f);
    o4.z = fmaxf(fmaf(acc.z * inv, sc.z, sh.z), 0.f);
    o4.w = fmaxf(fmaf(acc.w * inv, sc.w, sh.w), 0.f);
    ((float4*)outbuf)[(size_t)node * 32 + lane] = o4;
}

// ---------------- host orchestration ----------------
static void run_layer(const float* x_in, float* agg_out, __half* p_h,
                      const float* W, const float* asrc, const float* adst,
                      const float* bias, const float* gamma, const float* beta,
                      const float* mean, const float* var)
{
    gemm_dots_kernel<<<(NN + 127) / 128, 256, SMEM_GEMM_BYTES>>>(x_in, W, p_h, asrc, adst);
    agg_kernel<<<(NN * 32 + 255) / 256, 256>>>(agg_out, bias, gamma, beta, mean, var);
}

extern "C" void kernel_launch(void* const* d_in, const int* in_sizes, int n_in,
                              void* d_out, int out_size)
{
    const float* x     = (const float*)d_in[0];
    const int*   eidx  = (const int*)d_in[1];
    const float* Ws    = (const float*)d_in[2];
    const float* a_src = (const float*)d_in[3];
    const float* a_dst = (const float*)d_in[4];
    const float* bias  = (const float*)d_in[5];
    const float* gamma = (const float*)d_in[6];
    const float* beta  = (const float*)d_in[7];
    const float* mean  = (const float*)d_in[8];
    const float* var   = (const float*)d_in[9];
    float*       out   = (float*)d_out;

    const int* esrc = eidx;
    const int* edst = eidx + EE;

    __half* p_h; cudaGetSymbolAddress((void**)&p_h, g_h);
    float* p_x1; cudaGetSymbolAddress((void**)&p_x1, g_x1);

    cudaFuncSetAttribute(gemm_dots_kernel,
                         cudaFuncAttributeMaxDynamicSharedMemorySize, SMEM_GEMM_BYTES);

    csr_init_kernel<<<(NN + 255) / 256, 256>>>();
    csr_hist_kernel<<<(EE + 255) / 256, 256>>>(edst);
    scan_kernel<<<NB, 256>>>();
    csr_scatter_kernel<<<(ET + 255) / 256, 256>>>(esrc, edst);

    run_layer(x, p_x1, p_h, Ws, a_src, a_dst, bias, gamma, beta, mean, var);
    run_layer(p_x1, out, p_h,
              Ws + DD * DD, a_src + DD, a_dst + DD, bias + DD,
              gamma + DD, beta + DD, mean + DD, var + DD);
}

// round 11
// speedup vs baseline: 1.5821x; 1.0271x over previous
#include <cuda_runtime.h>
#include <cuda_fp16.h>
#include <math_constants.h>

#define NN 50000
#define EE 800000
#define DD 128
#define ET (EE + NN)
#define NB ((NN + 255) / 256)      // 196 scan blocks
#define BN_EPS 1e-12f
#define SLOPE 0.2f

#define LDH 136
#define SMEM_X_BYTES (128 * LDH * 2)
#define SMEM_GEMM_BYTES (2 * SMEM_X_BYTES + 256 * 4)

// ---------------- scratch ----------------
__device__ __align__(16) __half g_h  [NN * DD];  // h = x@W (fp16, gather path)
__device__ __align__(16) __half g_x1h[NN * DD];  // layer-1 output, fp16
__device__ float g_hs[NN];
__device__ float g_hd[NN];
__device__ int   g_rowoff[NN + 1];
__device__ int   g_eoff[EE];
__device__ int   g_csr[ET];

// zeroed by one cudaMemsetAsync each launch
struct CsrState {
    int cnt[NN];
    unsigned long long st[NB];
    unsigned bar;
    unsigned pad;
};
__device__ CsrState g_cs;

// ---------------- mma helpers ----------------
__device__ __forceinline__ unsigned smem_u32(const void* p) {
    return (unsigned)__cvta_generic_to_shared(p);
}
__device__ __forceinline__ void ldmA(unsigned addr, unsigned& a0, unsigned& a1,
                                     unsigned& a2, unsigned& a3) {
    asm volatile("ldmatrix.sync.aligned.m8n8.x4.shared.b16 {%0,%1,%2,%3}, [%4];"
                 : "=r"(a0), "=r"(a1), "=r"(a2), "=r"(a3) : "r"(addr));
}
__device__ __forceinline__ void ldmBT(unsigned addr, unsigned& b0, unsigned& b1) {
    asm volatile("ldmatrix.sync.aligned.m8n8.x2.trans.shared.b16 {%0,%1}, [%2];"
                 : "=r"(b0), "=r"(b1) : "r"(addr));
}
__device__ __forceinline__ void mma16816(float& d0, float& d1, float& d2, float& d3,
                                         unsigned a0, unsigned a1, unsigned a2, unsigned a3,
                                         unsigned b0, unsigned b1) {
    asm volatile("mma.sync.aligned.m16n8k16.row.col.f32.f16.f16.f32 "
                 "{%0,%1,%2,%3}, {%4,%5,%6,%7}, {%8,%9}, {%0,%1,%2,%3};"
                 : "+f"(d0), "+f"(d1), "+f"(d2), "+f"(d3)
                 : "r"(a0), "r"(a1), "r"(a2), "r"(a3), "r"(b0), "r"(b1));
}

// ============ GEMM via HMMA + fused attention dots; input fp32 or fp16 ============
template<bool HALF_IN>
__global__ __launch_bounds__(256) void gemm_dots_kernel(
    const void* __restrict__ Xv, const float* __restrict__ W,
    __half* __restrict__ H,
    const float* __restrict__ asrc, const float* __restrict__ adst)
{
    extern __shared__ char smem[];
    __half* sX = (__half*)smem;
    __half* sW = (__half*)(smem + SMEM_X_BYTES);
    float*  sA = (float*) (smem + 2 * SMEM_X_BYTES);

    const int tid  = threadIdx.x;
    const int wid  = tid >> 5;
    const int lane = tid & 31;
    const int row0 = blockIdx.x * 128;

    if (HALF_IN) {
        const __half* X = (const __half*)Xv;
#pragma unroll
        for (int it = 0; it < 8; it++) {
            int e  = it * 256 + tid;
            int r  = e >> 4, c8 = e & 15;          // 16 uint4 per 128-half row
            int gr = row0 + r;
            uint4 v = make_uint4(0u, 0u, 0u, 0u);
            if (gr < NN) v = *(const uint4*)&X[(size_t)gr * 128 + c8 * 8];
            *(uint4*)&sX[r * LDH + c8 * 8] = v;
        }
    } else {
        const float* X = (const float*)Xv;
#pragma unroll
        for (int it = 0; it < 16; it++) {
            int e  = it * 256 + tid;
            int r  = e >> 5, c4 = e & 31;
            int gr = row0 + r;
            float4 v = (gr < NN) ? *(const float4*)&X[(size_t)gr * 128 + c4 * 4]
                                 : make_float4(0.f, 0.f, 0.f, 0.f);
            __half2 h0 = __floats2half2_rn(v.x, v.y);
            __half2 h1 = __floats2half2_rn(v.z, v.w);
            *(uint2*)&sX[r * LDH + c4 * 4] = make_uint2(*(unsigned*)&h0, *(unsigned*)&h1);
        }
    }
#pragma unroll
    for (int it = 0; it < 16; it++) {
        int e = it * 256 + tid;
        int k = e >> 5, c4 = e & 31;
        float4 v = *(const float4*)&W[(size_t)k * 128 + c4 * 4];
        __half2 h0 = __floats2half2_rn(v.x, v.y);
        __half2 h1 = __floats2half2_rn(v.z, v.w);
        *(uint2*)&sW[k * LDH + c4 * 4] = make_uint2(*(unsigned*)&h0, *(unsigned*)&h1);
    }
    sA[tid] = (tid < 128) ? asrc[tid] : adst[tid - 128];
    __syncthreads();

    const int r0 = wid * 16;
    float d[16][4];
#pragma unroll
    for (int nt = 0; nt < 16; nt++)
#pragma unroll
        for (int j = 0; j < 4; j++) d[nt][j] = 0.f;

    unsigned aBase = smem_u32(&sX[(r0 + (lane & 15)) * LDH + 8 * (lane >> 4)]);
    unsigned wBase = smem_u32(sW);

#pragma unroll
    for (int k = 0; k < 8; k++) {
        unsigned a0, a1, a2, a3;
        ldmA(aBase + (16 * k) * 2, a0, a1, a2, a3);
        unsigned bRow = wBase + ((16 * k + (lane & 15)) * LDH) * 2;
#pragma unroll
        for (int nt = 0; nt < 16; nt++) {
            unsigned b0, b1;
            ldmBT(bRow + nt * 8 * 2, b0, b1);
            mma16816(d[nt][0], d[nt][1], d[nt][2], d[nt][3], a0, a1, a2, a3, b0, b1);
        }
    }

    const int qr   = lane >> 2;
    const int qc   = (lane & 3) * 2;
    const int rowA = row0 + r0 + qr;
    const int rowB = rowA + 8;
    float psA = 0.f, pdA = 0.f, psB = 0.f, pdB = 0.f;

#pragma unroll
    for (int nt = 0; nt < 16; nt++) {
        int c = nt * 8 + qc;
        float2 av = *(float2*)&sA[c];
        float2 bv = *(float2*)&sA[128 + c];
        psA += d[nt][0] * av.x + d[nt][1] * av.y;
        pdA += d[nt][0] * bv.x + d[nt][1] * bv.y;
        psB += d[nt][2] * av.x + d[nt][3] * av.y;
        pdB += d[nt][2] * bv.x + d[nt][3] * bv.y;
        if (rowA < NN) {
            __half2 hh = __floats2half2_rn(d[nt][0], d[nt][1]);
            *(__half2*)&H[(size_t)rowA * 128 + c] = hh;
        }
        if (rowB < NN) {
            __half2 hh = __floats2half2_rn(d[nt][2], d[nt][3]);
            *(__half2*)&H[(size_t)rowB * 128 + c] = hh;
        }
    }
#pragma unroll
    for (int o = 1; o <= 2; o <<= 1) {
        psA += __shfl_xor_sync(0xffffffffu, psA, o);
        pdA += __shfl_xor_sync(0xffffffffu, pdA, o);
        psB += __shfl_xor_sync(0xffffffffu, psB, o);
        pdB += __shfl_xor_sync(0xffffffffu, pdB, o);
    }
    if ((lane & 3) == 0) {
        if (rowA < NN) { g_hs[rowA] = psA; g_hd[rowA] = pdA; }
        if (rowB < NN) { g_hs[rowB] = psB; g_hd[rowB] = pdB; }
    }
}

// ================= CSR build =================
__global__ __launch_bounds__(256) void csr_hist_kernel(const int* __restrict__ edst)
{
    int t = blockIdx.x * blockDim.x + threadIdx.x;
    if (t < EE) g_eoff[t] = atomicAdd(&g_cs.cnt[edst[t]], 1);
}

__device__ __forceinline__ int block_incl_scan_256(int v, int tid)
{
    int lane = tid & 31, w = tid >> 5;
#pragma unroll
    for (int o = 1; o < 32; o <<= 1) {
        int n = __shfl_up_sync(0xffffffffu, v, o);
        if (lane >= o) v += n;
    }
    __shared__ int wsum[8];
    if (lane == 31) wsum[w] = v;
    __syncthreads();
    if (tid < 8) {
        int x = wsum[tid];
#pragma unroll
        for (int o = 1; o < 8; o <<= 1) {
            int n = __shfl_up_sync(0xffu, x, o);
            if (tid >= o) x += n;
        }
        wsum[tid] = x;
    }
    __syncthreads();
    if (w > 0) v += wsum[w - 1];
    return v;
}

// scan (decoupled lookback) + grid barrier + scatter, single kernel (196 blocks, all resident)
__global__ __launch_bounds__(256) void scan_scatter_kernel(
    const int* __restrict__ esrc, const int* __restrict__ edst)
{
    const int t = threadIdx.x, b = blockIdx.x;
    const int i = b * 256 + t;
    int v = (i < NN) ? g_cs.cnt[i] + 1 : 0;     // +1: self-loop slot
    int incl = block_incl_scan_256(v, t);

    __shared__ int s_agg;
    __shared__ int s_prefix;
    if (t == 255) s_agg = incl;
    if (b == 0 && t == 0) g_rowoff[0] = 0;
    __syncthreads();

    if (t == 0) {
        int agg = s_agg;
        if (b == 0) {
            *(volatile unsigned long long*)&g_cs.st[0] = (2ull << 32) | (unsigned)agg;
            s_prefix = 0;
        } else {
            *(volatile unsigned long long*)&g_cs.st[b] = (1ull << 32) | (unsigned)agg;
            int sum = 0;
            for (int p = b - 1; p >= 0; p--) {
                unsigned long long st;
                do { st = *(volatile unsigned long long*)&g_cs.st[p]; }
                while ((st >> 32) == 0ull);
                sum += (int)(st & 0xffffffffull);
                if ((st >> 32) == 2ull) break;
            }
            s_prefix = sum;
            *(volatile unsigned long long*)&g_cs.st[b] = (2ull << 32) | (unsigned)(sum + agg);
        }
    }
    __syncthreads();
    if (i < NN) g_rowoff[i + 1] = incl + s_prefix;

    // grid barrier (all NB blocks co-resident: tiny smem, 256 threads)
    __threadfence();
    __syncthreads();
    if (t == 0) {
        atomicAdd(&g_cs.bar, 1u);
        while (*(volatile unsigned*)&g_cs.bar < (unsigned)NB) {}
    }
    __syncthreads();
    __threadfence();

    // scatter: self loop at slot 0, edge e at rowoff[d] + 1 + eoff[e]
    for (int e = b * 256 + t; e < ET; e += NB * 256) {
        if (e < EE) {
            int d = edst[e];
            g_csr[g_rowoff[d] + 1 + g_eoff[e]] = esrc[e];
        } else {
            int n = e - EE;
            g_csr[g_rowoff[n]] = n;
        }
    }
}

// ========== fused: softmax (shift-invariant, m=0) aggregate + bias + BN + ReLU ==========
template<bool HALF_OUT>
__global__ __launch_bounds__(256) void agg_kernel(
    void* __restrict__ outv,
    const float* __restrict__ bias,  const float* __restrict__ gamma,
    const float* __restrict__ beta,  const float* __restrict__ mean,
    const float* __restrict__ var)
{
    int node = (int)(((size_t)blockIdx.x * blockDim.x + threadIdx.x) >> 5);
    int lane = threadIdx.x & 31;
    if (node >= NN) return;

    const int off = g_rowoff[node];
    const int end = g_rowoff[node + 1];
    const float hd_d = g_hd[node];

    float ssum = 0.f;
    float4 acc = make_float4(0.f, 0.f, 0.f, 0.f);

    for (int base = off; base < end; base += 32) {
        int rem = end - base; if (rem > 32) rem = 32;
        int s = 0; float ee = 0.f;
        if (lane < rem) {
            s = g_csr[base + lane];
            float e = g_hs[s] + hd_d;
            e = e > 0.f ? e : SLOPE * e;
            ee = __expf(e);          // scores O(1-10): no max shift needed
            ssum += ee;
        }
        if (rem == 32) {
#pragma unroll 16
            for (int j = 0; j < 32; j++) {
                int   sj  = __shfl_sync(0xffffffffu, s,  j);
                float eej = __shfl_sync(0xffffffffu, ee, j);
                uint2 pk = *(const uint2*)&g_h[(size_t)sj * 128 + lane * 4];
                float2 f0 = __half22float2(*(__half2*)&pk.x);
                float2 f1 = __half22float2(*(__half2*)&pk.y);
                acc.x += eej * f0.x; acc.y += eej * f0.y;
                acc.z += eej * f1.x; acc.w += eej * f1.y;
            }
        } else {
            for (int j = 0; j < rem; j++) {
                int   sj  = __shfl_sync(0xffffffffu, s,  j);
                float eej = __shfl_sync(0xffffffffu, ee, j);
                uint2 pk = *(const uint2*)&g_h[(size_t)sj * 128 + lane * 4];
                float2 f0 = __half22float2(*(__half2*)&pk.x);
                float2 f1 = __half22float2(*(__half2*)&pk.y);
                acc.x += eej * f0.x; acc.y += eej * f0.y;
                acc.z += eej * f1.x; acc.w += eej * f1.y;
            }
        }
    }
#pragma unroll
    for (int o = 16; o; o >>= 1) ssum += __shfl_xor_sync(0xffffffffu, ssum, o);
    float inv = 1.f / ssum;

    float4 ga = ((const float4*)gamma)[lane];
    float4 va = ((const float4*)var)[lane];
    float4 bi = ((const float4*)bias)[lane];
    float4 mu = ((const float4*)mean)[lane];
    float4 be = ((const float4*)beta)[lane];
    float4 sc, sh, o4;
    sc.x = ga.x * rsqrtf(va.x + BN_EPS); sh.x = (bi.x - mu.x) * sc.x + be.x;
    sc.y = ga.y * rsqrtf(va.y + BN_EPS); sh.y = (bi.y - mu.y) * sc.y + be.y;
    sc.z = ga.z * rsqrtf(va.z + BN_EPS); sh.z = (bi.z - mu.z) * sc.z + be.z;
    sc.w = ga.w * rsqrtf(va.w + BN_EPS); sh.w = (bi.w - mu.w) * sc.w + be.w;
    o4.x = fmaxf(fmaf(acc.x * inv, sc.x, sh.x), 0.f);
    o4.y = fmaxf(fmaf(acc.y * inv, sc.y, sh.y), 0.f);
    o4.z = fmaxf(fmaf(acc.z * inv, sc.z, sh.z), 0.f);
    o4.w = fmaxf(fmaf(acc.w * inv, sc.w, sh.w), 0.f);

    if (HALF_OUT) {
        __half2 q0 = __floats2half2_rn(o4.x, o4.y);
        __half2 q1 = __floats2half2_rn(o4.z, o4.w);
        *(uint2*)&((__half*)outv)[(size_t)node * 128 + lane * 4] =
            make_uint2(*(unsigned*)&q0, *(unsigned*)&q1);
    } else {
        ((float4*)outv)[(size_t)node * 32 + lane] = o4;
    }
}

// ---------------- host orchestration ----------------
extern "C" void kernel_launch(void* const* d_in, const int* in_sizes, int n_in,
                              void* d_out, int out_size)
{
    const float* x     = (const float*)d_in[0];
    const int*   eidx  = (const int*)d_in[1];
    const float* Ws    = (const float*)d_in[2];
    const float* a_src = (const float*)d_in[3];
    const float* a_dst = (const float*)d_in[4];
    const float* bias  = (const float*)d_in[5];
    const float* gamma = (const float*)d_in[6];
    const float* beta  = (const float*)d_in[7];
    const float* mean  = (const float*)d_in[8];
    const float* var   = (const float*)d_in[9];
    float*       out   = (float*)d_out;

    const int* esrc = eidx;
    const int* edst = eidx + EE;

    __half* p_h;   cudaGetSymbolAddress((void**)&p_h,  g_h);
    __half* p_x1h; cudaGetSymbolAddress((void**)&p_x1h, g_x1h);
    void*   p_cs;  cudaGetSymbolAddress(&p_cs, g_cs);

    cudaFuncSetAttribute(gemm_dots_kernel<false>,
                         cudaFuncAttributeMaxDynamicSharedMemorySize, SMEM_GEMM_BYTES);
    cudaFuncSetAttribute(gemm_dots_kernel<true>,
                         cudaFuncAttributeMaxDynamicSharedMemorySize, SMEM_GEMM_BYTES);

    cudaMemsetAsync(p_cs, 0, sizeof(CsrState));
    csr_hist_kernel<<<(EE + 255) / 256, 256>>>(edst);
    scan_scatter_kernel<<<NB, 256>>>(esrc, edst);

    // layer 0
    gemm_dots_kernel<false><<<(NN + 127) / 128, 256, SMEM_GEMM_BYTES>>>(
        x, Ws, p_h, a_src, a_dst);
    agg_kernel<true><<<(NN * 32 + 255) / 256, 256>>>(p_x1h, bias, gamma, beta, mean, var);

    // layer 1
    gemm_dots_kernel<true><<<(NN + 127) / 128, 256, SMEM_GEMM_BYTES>>>(
        p_x1h, Ws + DD * DD, p_h, a_src + DD, a_dst + DD);
    agg_kernel<false><<<(NN * 32 + 255) / 256, 256>>>(out, bias + DD, gamma + DD,
                                                      beta + DD, mean + DD, var + DD);
}